// round 1
// baseline (speedup 1.0000x reference)
#include <cuda_runtime.h>
#include <cstdint>

// TaylorExp: x [4,16,4096,16] f32 -> out [4,16,4096,273] f32
// out_row = [1, x*0.5, vec(x x^T) * (1/(4*sqrt(2)))]
//
// Strategy: process 4 rows per warp ("group"). 4*273 = 1092 floats = 273
// aligned float4 stores (group byte offset 4368 is 16B aligned). Inputs are
// staged in shared memory pre-scaled by 0.5, so:
//   linear term  = s[f-1]
//   quad term    = s[i]*s[j] * (1/sqrt(2))   (0.25 * (1/sqrt2) = 1/(4*sqrt2))

#define WARPS_PER_BLOCK 8
#define THREADS (WARPS_PER_BLOCK * 32)

static constexpr int TOTAL_ROWS   = 4 * 16 * 4096;     // 262144
static constexpr int GROUPS       = TOTAL_ROWS / 4;    // 65536
static constexpr int OUT_PER_GRP  = 4 * 273;           // 1092 floats
static constexpr int VEC_PER_GRP  = OUT_PER_GRP / 4;   // 273 float4

__global__ __launch_bounds__(THREADS)
void TaylorExp_14783277432863_kernel(const float* __restrict__ x,
                                     float* __restrict__ out) {
    __shared__ float s[WARPS_PER_BLOCK][64];   // 4 rows * 16 floats, pre-scaled

    const int warp = threadIdx.x >> 5;
    const int lane = threadIdx.x & 31;
    const int group = blockIdx.x * WARPS_PER_BLOCK + warp;   // grid is exact

    // ---- load 4 rows (64 floats) as 16 float4, pre-scale by 0.5 ----
    const float4* xg = reinterpret_cast<const float4*>(x) + (size_t)group * 16;
    if (lane < 16) {
        float4 v = __ldg(&xg[lane]);
        v.x *= 0.5f; v.y *= 0.5f; v.z *= 0.5f; v.w *= 0.5f;
        reinterpret_cast<float4*>(s[warp])[lane] = v;
    }
    __syncwarp();

    const float* sw = s[warp];
    float4* og = reinterpret_cast<float4*>(out) + (size_t)group * VEC_PER_GRP;
    const float QSCALE = 0.70710678118654752f;   // 1/sqrt(2)

    #pragma unroll
    for (int it = 0; it < 9; ++it) {
        const int k = lane + it * 32;          // float4 index within group
        if (it < 8 || k < VEC_PER_GRP) {       // 273 = 8*32 + 17
            float4 v;
            float* vp = reinterpret_cast<float*>(&v);
            const int e = k << 2;              // element index within group
            #pragma unroll
            for (int c = 0; c < 4; ++c) {
                const int ec  = e + c;
                const int row = (ec >= 273) + (ec >= 546) + (ec >= 819);
                const int f   = ec - row * 273;
                const float* b = sw + (row << 4);
                float val;
                if (f == 0) {
                    val = 1.0f;
                } else if (f <= 16) {
                    val = b[f - 1];
                } else {
                    const int q = f - 17;
                    val = b[q >> 4] * b[q & 15] * QSCALE;
                }
                vp[c] = val;
            }
            og[k] = v;
        }
    }
}

extern "C" void kernel_launch(void* const* d_in, const int* in_sizes, int n_in,
                              void* d_out, int out_size) {
    const float* x = (const float*)d_in[0];
    float* out = (float*)d_out;
    (void)in_sizes; (void)n_in; (void)out_size;

    const int blocks = GROUPS / WARPS_PER_BLOCK;   // 8192
    TaylorExp_14783277432863_kernel<<<blocks, THREADS>>>(x, out);
}

// round 2
// speedup vs baseline: 1.0085x; 1.0085x over previous
#include <cuda_runtime.h>
#include <cstdint>

// TaylorExp: x [4,16,4096,16] f32 -> out [4,16,4096,273] f32
// out_row = [1, 0.5*x, vec(x x^T) / (4*sqrt(2))]
//
// R2: table-driven decode. Every output element is PQ[offA]*PQ[offB] where
// PQ is a per-warp 136-float array: P (68 floats: per-row [1.0, 0.5*x[0..15]])
// followed by Q (68 floats: per-row [1.0, (0.5/sqrt2)*x[0..15]]).
// A block-shared 273-entry uint4 table packs the two byte offsets (16b each)
// for all 4 elements of each float4. No branches/compares in the hot loop.

#define WARPS_PER_BLOCK 8
#define THREADS (WARPS_PER_BLOCK * 32)

static constexpr int TOTAL_ROWS  = 4 * 16 * 4096;   // 262144
static constexpr int GROUPS      = TOTAL_ROWS / 4;  // 65536 (4 rows per warp)
static constexpr int VEC_PER_GRP = 273;             // float4 per group (4*273/4)

__device__ __forceinline__ float lds_f32(unsigned addr) {
    float v;
    asm volatile("ld.shared.f32 %0, [%1];" : "=f"(v) : "r"(addr));
    return v;
}

__global__ __launch_bounds__(THREADS)
void TaylorExp_14783277432863_kernel(const float* __restrict__ x,
                                     float* __restrict__ out) {
    __shared__ uint4 tab[273];                     // 4368 B, block-shared
    __shared__ float pq[WARPS_PER_BLOCK][136];     // P[68] | Q[68] per warp

    const int tid  = threadIdx.x;
    const int warp = tid >> 5;
    const int lane = tid & 31;
    const int group = blockIdx.x * WARPS_PER_BLOCK + warp;   // grid exact

    // ---- build offset table (identical for all groups) ----
    for (int k = tid; k < 273; k += THREADS) {
        unsigned w[4];
        #pragma unroll
        for (int c = 0; c < 4; ++c) {
            const int ec  = 4 * k + c;
            const int row = (ec >= 273) + (ec >= 546) + (ec >= 819);
            const int f   = ec - row * 273;
            int ia, ib;                 // float indices into pq[warp][136]
            if (f == 0)       { ia = row * 17;          ib = 68 + row * 17; }
            else if (f <= 16) { ia = row * 17 + f;      ib = 68 + row * 17; }
            else {
                const int q = f - 17;
                ia = row * 17 + 1 + (q >> 4);
                ib = 68 + row * 17 + 1 + (q & 15);
            }
            w[c] = (unsigned)(ia * 4) | ((unsigned)(ib * 4) << 16);  // byte offs
        }
        tab[k] = make_uint4(w[0], w[1], w[2], w[3]);
    }

    // ---- fill per-warp P/Q (pre-scaled inputs) ----
    const float4* xg = reinterpret_cast<const float4*>(x) + (size_t)group * 16;
    if (lane < 16) {
        float4 v = __ldg(&xg[lane]);
        const int row = lane >> 2, part = lane & 3;
        float* P = pq[warp];
        float* Q = pq[warp] + 68;
        const int bi = row * 17 + 1 + part * 4;
        P[bi + 0] = 0.5f * v.x;  P[bi + 1] = 0.5f * v.y;
        P[bi + 2] = 0.5f * v.z;  P[bi + 3] = 0.5f * v.w;
        const float c2 = 0.5f * 0.70710678118654752f;
        Q[bi + 0] = c2 * v.x;    Q[bi + 1] = c2 * v.y;
        Q[bi + 2] = c2 * v.z;    Q[bi + 3] = c2 * v.w;
    }
    if (lane < 4) {                          // unit entries for const/linear
        pq[warp][lane * 17]      = 1.0f;     // P row heads
        pq[warp][68 + lane * 17] = 1.0f;     // Q row heads
    }
    __syncthreads();

    const unsigned sb =
        (unsigned)__cvta_generic_to_shared(&pq[warp][0]);
    float4* og = reinterpret_cast<float4*>(out) + (size_t)group * VEC_PER_GRP;

    #pragma unroll
    for (int it = 0; it < 9; ++it) {
        const int k = lane + it * 32;
        if (it < 8 || k < VEC_PER_GRP) {     // 273 = 8*32 + 17
            const uint4 cd = tab[k];
            float4 v;
            v.x = lds_f32(sb + (cd.x & 0xFFFFu)) * lds_f32(sb + (cd.x >> 16));
            v.y = lds_f32(sb + (cd.y & 0xFFFFu)) * lds_f32(sb + (cd.y >> 16));
            v.z = lds_f32(sb + (cd.z & 0xFFFFu)) * lds_f32(sb + (cd.z >> 16));
            v.w = lds_f32(sb + (cd.w & 0xFFFFu)) * lds_f32(sb + (cd.w >> 16));
            og[k] = v;
        }
    }
}

extern "C" void kernel_launch(void* const* d_in, const int* in_sizes, int n_in,
                              void* d_out, int out_size) {
    const float* x = (const float*)d_in[0];
    float* out = (float*)d_out;
    (void)in_sizes; (void)n_in; (void)out_size;

    const int blocks = GROUPS / WARPS_PER_BLOCK;   // 8192
    TaylorExp_14783277432863_kernel<<<blocks, THREADS>>>(x, out);
}